// round 9
// baseline (speedup 1.0000x reference)
#include <cuda_runtime.h>
#include <cstdint>
#include <math.h>

#define Bb 8
#define Nn 4096
#define Cc 512
#define Kk 150
#define MROWS (Bb*Nn)
#define QCW 480          // qcat/kcat row width (3 x 160)

// ---------------- scratch (device globals; no allocation allowed) -----------
__device__ float g_Xcat[(size_t)MROWS*1536]; // [x_hi | x_hi | x_lo] (tf32)
__device__ float g_Wcat[(size_t)300*1536];   // Wq,Wk rows; [hi|lo|hi] (tf32)
__device__ float g_bqk [512];
__device__ float g_Qcat[(size_t)MROWS*QCW];  // [hi|hi|lo] (tf32)
__device__ float g_Kcat[(size_t)MROWS*QCW];  // [hi|lo|hi] (tf32)
__device__ float g_Vt  [(size_t)Cc*MROWS];   // v^T (512, 32768), tf32-rounded
__device__ float g_S   [(size_t)Bb*Nn*Nn];   // raw scores fp32
__device__ float g_O   [(size_t)Bb*Nn*Cc];   // attn out, tf32-rounded
__device__ float g_Rmax[(size_t)MROWS];
__device__ float g_Rinv[(size_t)MROWS];

// ---------------- helpers ----------------------------------------------------
__device__ __forceinline__ uint32_t f2tf(float v) {
    uint32_t u; asm("cvt.rna.tf32.f32 %0, %1;" : "=r"(u) : "f"(v)); return u;
}

__device__ __forceinline__ void mma8(float* c, const uint32_t* a,
                                     uint32_t b0, uint32_t b1) {
    asm volatile(
        "mma.sync.aligned.m16n8k8.row.col.f32.tf32.tf32.f32 "
        "{%0,%1,%2,%3}, {%4,%5,%6,%7}, {%8,%9}, {%0,%1,%2,%3};"
        : "+f"(c[0]), "+f"(c[1]), "+f"(c[2]), "+f"(c[3])
        : "r"(a[0]), "r"(a[1]), "r"(a[2]), "r"(a[3]), "r"(b0), "r"(b1));
}

// ---------------------------------------------------------------------------
// tf32 mma GEMM:  C[m,n] = sum_k A[m,k] * B[n,k]
// Tile 128x128x32, 8 warps (2m x 4n), warp tile 64x32, double-buffered smem.
// Lane map with consistent k-permutation (hw col t <-> logical 2t,
// hw col t+4 <-> logical 2t+1, applied to BOTH operands -> dot invariant):
//   thread L (g=L>>2, t=L&3) fetches rows g,g+8 at k=2t,2t+1 (two float2).
//   A reg order: a0=A[g][2t], a1=A[g+8][2t], a2=A[g][2t+1], a3=A[g+8][2t+1]
//     (hw reads a0/a2 as row g, a1/a3 as row g+8 -> pack (x,z,y,w)).
//   B reg order: b0=B[n][2t], b1=B[n][2t+1]; uint4 packs n-groups g and g+8.
//   smem slot addr ((frag*4+ks)*32 + L^ks)*4, one STS.128 per slot.
// CVTA/CVTB: convert input to tf32 (skip when already rounded).
// Modes: rmaxA (exp(a - rmax) on A), qcat (QK epilogue), transLd, roundOut.
// ---------------------------------------------------------------------------
template<bool CVTA, bool CVTB>
__global__ void __launch_bounds__(256, 2)
gemm_mma(const float* __restrict__ A, const float* __restrict__ Bm,
         float* __restrict__ C, int M, int Ncols, int Kd, int lda, int ldb,
         size_t sA, size_t sB, size_t sC,
         const float* __restrict__ bias, const float* __restrict__ rowscale,
         const float* __restrict__ resid, const float* __restrict__ gammaPtr,
         long long transLd, int roundOut,
         const float* __restrict__ rmaxA,
         float* __restrict__ qcat, float* __restrict__ kcat)
{
    extern __shared__ __align__(16) float smf[];
    __shared__ float srmax[128];

    const int tid  = threadIdx.x;
    const int wid  = tid >> 5;
    const int lane = tid & 31;
    const int wm   = wid >> 2;
    const int wn   = wid & 3;
    const int bz   = blockIdx.z;
    A  += (size_t)bz * sA;
    Bm += (size_t)bz * sB;
    C  += (size_t)bz * sC;
    const int m0 = blockIdx.y * 128;
    const int n0 = blockIdx.x * 128;

    const int BUFSZ = 8192;   // floats per buffer
    const int OFFB  = 4096;

    if (rmaxA && tid < 128)
        srmax[tid] = rmaxA[(size_t)bz * M + m0 + tid];

    float acc[4][4][4];
#pragma unroll
    for (int i = 0; i < 4; i++)
#pragma unroll
        for (int j = 0; j < 4; j++)
#pragma unroll
            for (int r = 0; r < 4; r++) acc[i][j][r] = 0.f;

    const int nch = Kd >> 5;
    float4 pa[4], pb[4];

    const int L  = tid & 31;
    const int g2 = (L >> 2);        // 0..7
    const int t2 = (L & 3) << 1;    // 2t

    auto FETCHA = [&](int ch) {
        const int k0 = ch << 5;
#pragma unroll
        for (int s = 0; s < 4; s++) {
            int slot = s * 256 + tid;
            int ks = (slot >> 5) & 3, fm = slot >> 7;
            int k = k0 + (ks << 3) + t2;
            const float* p = A + (size_t)(m0 + fm * 16 + g2) * lda + k;
            float2 u = *(const float2*)p;
            float2 w = *(const float2*)(p + (size_t)8 * lda);
            pa[s] = make_float4(u.x, u.y, w.x, w.y);
        }
    };
    auto FETCHB = [&](int ch) {
        const int k0 = ch << 5;
#pragma unroll
        for (int s = 0; s < 4; s++) {
            int slot = s * 256 + tid;
            int ks = (slot >> 5) & 3, fnp = slot >> 7;
            int k = k0 + (ks << 3) + t2;
            int ne = n0 + fnp * 16 + g2;
            float2 u = make_float2(0.f, 0.f), w = make_float2(0.f, 0.f);
            const float* p = Bm + (size_t)ne * ldb + k;
            if (ne < Ncols)     u = *(const float2*)p;
            if (ne + 8 < Ncols) w = *(const float2*)(p + (size_t)8 * ldb);
            pb[s] = make_float4(u.x, u.y, w.x, w.y);
        }
    };

    auto STOREA = [&](int buf) {
        uint32_t* dst = (uint32_t*)(smf + buf * BUFSZ);
#pragma unroll
        for (int s = 0; s < 4; s++) {
            int slot = s * 256 + tid;
            int ks = (slot >> 5) & 3, fm = slot >> 7;
            float4 v = pa[s];   // (A[g][2t], A[g][2t+1], A[g+8][2t], A[g+8][2t+1])
            if (rmaxA) {
                float mx0 = srmax[fm * 16 + g2];
                float mx1 = srmax[fm * 16 + g2 + 8];
                v.x = __expf(v.x - mx0); v.y = __expf(v.y - mx0);
                v.z = __expf(v.z - mx1); v.w = __expf(v.w - mx1);
            }
            // reg order a0..a3 = (x, z, y, w): rows alternate g, g+8
            uint4 o;
            if (CVTA || rmaxA)
                o = make_uint4(f2tf(v.x), f2tf(v.z), f2tf(v.y), f2tf(v.w));
            else
                o = make_uint4(__float_as_uint(v.x), __float_as_uint(v.z),
                               __float_as_uint(v.y), __float_as_uint(v.w));
            *(uint4*)(dst + (((fm * 4 + ks) * 32) + (L ^ ks)) * 4) = o;
        }
    };
    auto STOREB = [&](int buf) {
        uint32_t* dst = (uint32_t*)(smf + buf * BUFSZ + OFFB);
#pragma unroll
        for (int s = 0; s < 4; s++) {
            int slot = s * 256 + tid;
            int ks = (slot >> 5) & 3, fnp = slot >> 7;
            float4 v = pb[s];   // (b0,b1) n-group g then n-group g+8
            uint4 o;
            if (CVTB)
                o = make_uint4(f2tf(v.x), f2tf(v.y), f2tf(v.z), f2tf(v.w));
            else
                o = make_uint4(__float_as_uint(v.x), __float_as_uint(v.y),
                               __float_as_uint(v.z), __float_as_uint(v.w));
            *(uint4*)(dst + (((fnp * 4 + ks) * 32) + (L ^ ks)) * 4) = o;
        }
    };

    auto COMPUTE = [&](int buf, int ks0, int ks1) {
        const uint32_t* base = (const uint32_t*)(smf + buf * BUFSZ);
#pragma unroll
        for (int ks = ks0; ks < ks1; ks++) {
            const int lsw = lane ^ ks;
            uint4 ah[4], bh[2];
#pragma unroll
            for (int i = 0; i < 4; i++)
                ah[i] = *(const uint4*)(base + (((wm * 4 + i) * 4 + ks) * 32 + lsw) * 4);
#pragma unroll
            for (int p = 0; p < 2; p++)
                bh[p] = *(const uint4*)(base + OFFB + (((wn * 2 + p) * 4 + ks) * 32 + lsw) * 4);
#pragma unroll
            for (int i = 0; i < 4; i++)
#pragma unroll
                for (int f = 0; f < 4; f++) {
                    const uint4& B4 = bh[f >> 1];
                    uint32_t b0 = (f & 1) ? B4.z : B4.x;
                    uint32_t b1 = (f & 1) ? B4.w : B4.y;
                    mma8(acc[i][f], (const uint32_t*)&ah[i], b0, b1);
                }
        }
    };

    __syncthreads();                 // srmax visible
    FETCHA(0); STOREA(0);
    FETCHB(0); STOREB(0);
    __syncthreads();
    for (int i = 0; i < nch; i++) {
        bool have = (i + 1) < nch;
        if (have) FETCHA(i + 1);
        COMPUTE(i & 1, 0, 2);
        if (have) { STOREA((i + 1) & 1); FETCHB(i + 1); }
        COMPUTE(i & 1, 2, 4);
        if (have) STOREB((i + 1) & 1);
        __syncthreads();
    }

    // ---- epilogue: stage in smem (pitch 132), fused coalesced write ---------
    float* stage = smf;
    const int g4 = lane >> 2, t4 = lane & 3;
#pragma unroll
    for (int i = 0; i < 4; i++) {
#pragma unroll
        for (int f = 0; f < 4; f++) {
            int ml = wm * 64 + i * 16 + g4;
            int nl = wn * 32 + f * 8 + t4 * 2;
            *(float2*)&stage[ml * 132 + nl]       = make_float2(acc[i][f][0], acc[i][f][1]);
            *(float2*)&stage[(ml + 8) * 132 + nl] = make_float2(acc[i][f][2], acc[i][f][3]);
        }
    }
    __syncthreads();

    if (qcat) {
#pragma unroll 4
        for (int t = 0; t < 64; t++) {
            int idx = t * 256 + tid;
            int nn = idx & 127, mm = idx >> 7;
            int n = n0 + nn, m = m0 + mm;
            if (n < Ncols) {
                float vb = stage[mm * 132 + nn] + __ldg(bias + n);
                float hi = __uint_as_float(f2tf(vb));
                float lo = __uint_as_float(f2tf(vb - hi));
                if (n < Kk) {
                    C[(size_t)m * Kk + n] = vb;                 // segmap
                    qcat[(size_t)m * QCW + n]       = hi;
                    qcat[(size_t)m * QCW + 160 + n] = hi;
                    qcat[(size_t)m * QCW + 320 + n] = lo;
                } else {
                    int nk = n - Kk;
                    kcat[(size_t)m * QCW + nk]       = hi;
                    kcat[(size_t)m * QCW + 160 + nk] = lo;
                    kcat[(size_t)m * QCW + 320 + nk] = hi;
                }
            }
        }
        return;
    }

    const float gm = gammaPtr ? *gammaPtr : 0.f;
#pragma unroll 4
    for (int t = 0; t < 64; t++) {
        int idx = t * 256 + tid;
        int mm, nn;
        if (transLd) { mm = idx & 127; nn = idx >> 7; }
        else         { nn = idx & 127; mm = idx >> 7; }
        int n = n0 + nn, m = m0 + mm;
        if (n < Ncols) {
            float v = stage[mm * 132 + nn];
            if (bias)     v += __ldg(bias + n);
            if (rowscale) v *= rowscale[(size_t)bz * M + m];
            if (roundOut) v = __uint_as_float(f2tf(v));
            if (resid)    v = gm * v + resid[(size_t)m * Ncols + n];
            if (transLd)  C[(size_t)n * transLd + m] = v;
            else          C[(size_t)m * Ncols + n]   = v;
        }
    }
}

// ---------------------------------------------------------------------------
// Prep kernels
// ---------------------------------------------------------------------------
__global__ void split_x_kernel(const float* __restrict__ x,
                               float* __restrict__ xcat)
{
    int idx = blockIdx.x * 256 + threadIdx.x;
    if (idx >= MROWS * Cc) return;
    int row = idx >> 9, col = idx & 511;
    float v = x[idx];
    float hi = __uint_as_float(f2tf(v));
    float lo = __uint_as_float(f2tf(v - hi));
    size_t b = (size_t)row * 1536 + col;
    xcat[b] = hi; xcat[b + 512] = hi; xcat[b + 1024] = lo;
}

__global__ void prep_w_kernel(const float* __restrict__ Wq,
                              const float* __restrict__ Wk,
                              const float* __restrict__ bq,
                              const float* __restrict__ bk,
                              float* __restrict__ wcat,
                              float* __restrict__ bqk)
{
    int idx = blockIdx.x * 256 + threadIdx.x;
    if (idx < 300 * 512) {
        int r = idx >> 9, c = idx & 511;
        float v = (r < Kk) ? Wq[r * 512 + c] : Wk[(r - Kk) * 512 + c];
        float hi = __uint_as_float(f2tf(v));
        float lo = __uint_as_float(f2tf(v - hi));
        size_t b = (size_t)r * 1536 + c;
        wcat[b] = hi; wcat[b + 512] = lo; wcat[b + 1024] = hi;
    }
    if (idx < 300) bqk[idx] = (idx < Kk) ? bq[idx] : bk[idx - Kk];
}

__global__ void zero_pads_kernel(float* __restrict__ qcat,
                                 float* __restrict__ kcat)
{
    int row = blockIdx.x;
    int t = threadIdx.x;
    if (t < 30) {
        int col = Kk + (t % 10) + (t / 10) * 160;
        qcat[(size_t)row * QCW + col] = 0.f;
        kcat[(size_t)row * QCW + col] = 0.f;
    }
}

// ---------------------------------------------------------------------------
// Row stats: max and 1/sum(exp(v - max)) per row of S (no write-back).
// ---------------------------------------------------------------------------
__global__ __launch_bounds__(256)
void rowstat_kernel(const float* __restrict__ S,
                    float* __restrict__ rmax, float* __restrict__ rinv)
{
    const size_t row = blockIdx.x;
    const float* p = S + row * (size_t)Nn;
    const int tid = threadIdx.x;

    float v[16];
    float mx = -3.4e38f;
#pragma unroll
    for (int i = 0; i < 16; i++) {
        v[i] = p[tid + i * 256];
        mx = fmaxf(mx, v[i]);
    }
    __shared__ float red[256];
    red[tid] = mx;
    __syncthreads();
    for (int s = 128; s > 0; s >>= 1) {
        if (tid < s) red[tid] = fmaxf(red[tid], red[tid + s]);
        __syncthreads();
    }
    mx = red[0];
    __syncthreads();

    float sum = 0.f;
#pragma unroll
    for (int i = 0; i < 16; i++) sum += __expf(v[i] - mx);
    red[tid] = sum;
    __syncthreads();
    for (int s = 128; s > 0; s >>= 1) {
        if (tid < s) red[tid] += red[tid + s];
        __syncthreads();
    }
    if (tid == 0) { rmax[row] = mx; rinv[row] = 1.f / red[0]; }
}

// ---------------------------------------------------------------------------
#define SMEM_SZ (128*132*4)   // 67584 B >= 2 k-buffers (65536 B)

extern "C" void kernel_launch(void* const* d_in, const int* in_sizes, int n_in,
                              void* d_out, int out_size)
{
    (void)in_sizes; (void)n_in; (void)out_size;
    const float* x     = (const float*)d_in[0];
    const float* Wq    = (const float*)d_in[1];
    const float* bq    = (const float*)d_in[2];
    const float* Wk    = (const float*)d_in[3];
    const float* bk    = (const float*)d_in[4];
    const float* Wv    = (const float*)d_in[5];
    const float* bv    = (const float*)d_in[6];
    const float* Wres  = (const float*)d_in[7];
    const float* bres  = (const float*)d_in[8];
    const float* gamma = (const float*)d_in[9];

    float* out     = (float*)d_out;
    float* segmap  = out;                          // (B,N,K)
    float* featmap = out + (size_t)Bb * Nn * Kk;   // (B,N,C)

    float *pXcat, *pWcat, *pbqk, *pQcat, *pKcat, *pVt, *pS, *pO, *pRmax, *pRinv;
    cudaGetSymbolAddress((void**)&pXcat, g_Xcat);
    cudaGetSymbolAddress((void**)&pWcat, g_Wcat);
    cudaGetSymbolAddress((void**)&pbqk,  g_bqk);
    cudaGetSymbolAddress((void**)&pQcat, g_Qcat);
    cudaGetSymbolAddress((void**)&pKcat, g_Kcat);
    cudaGetSymbolAddress((void**)&pVt,   g_Vt);
    cudaGetSymbolAddress((void**)&pS,    g_S);
    cudaGetSymbolAddress((void**)&pO,    g_O);
    cudaGetSymbolAddress((void**)&pRmax, g_Rmax);
    cudaGetSymbolAddress((void**)&pRinv, g_Rinv);

    cudaFuncSetAttribute(gemm_mma<true,true>,
        cudaFuncAttributeMaxDynamicSharedMemorySize, SMEM_SZ);
    cudaFuncSetAttribute(gemm_mma<false,false>,
        cudaFuncAttributeMaxDynamicSharedMemorySize, SMEM_SZ);
    cudaFuncSetAttribute(gemm_mma<true,false>,
        cudaFuncAttributeMaxDynamicSharedMemorySize, SMEM_SZ);
    cudaFuncSetAttribute(gemm_mma<false,true>,
        cudaFuncAttributeMaxDynamicSharedMemorySize, SMEM_SZ);

    // --- prep: split x / weights, zero cat-pads -----------------------------
    split_x_kernel<<<(MROWS * Cc + 255) / 256, 256>>>(x, pXcat);
    prep_w_kernel<<<(300 * 512 + 255) / 256, 256>>>(Wq, Wk, bq, bk, pWcat, pbqk);
    zero_pads_kernel<<<MROWS, 32>>>(pQcat, pKcat);

    // --- v = x @ Wv^T + bv, stored transposed (C, B*N), tf32-rounded --------
    gemm_mma<true,true><<<dim3(4, 256, 1), 256, SMEM_SZ>>>(
        x, Wv, pVt, MROWS, Cc, Cc, Cc, Cc, 0, 0, 0,
        bv, nullptr, nullptr, nullptr, (long long)MROWS, 1,
        nullptr, nullptr, nullptr);

    // --- Q,K projections (exact 3xTF32 via cat-K), inputs pre-rounded -------
    gemm_mma<false,false><<<dim3(3, 256, 1), 256, SMEM_SZ>>>(
        pXcat, pWcat, segmap, MROWS, 300, 1536, 1536, 1536, 0, 0, 0,
        pbqk, nullptr, nullptr, nullptr, 0, 0,
        nullptr, pQcat, pKcat);

    // --- S = Qcat @ Kcat^T per batch (Kd=480), no cvt anywhere ---------------
    gemm_mma<false,false><<<dim3(32, 32, Bb), 256, SMEM_SZ>>>(
        pQcat, pKcat, pS, Nn, Nn, QCW, QCW, QCW,
        (size_t)Nn * QCW, (size_t)Nn * QCW, (size_t)Nn * Nn,
        nullptr, nullptr, nullptr, nullptr, 0, 0,
        nullptr, nullptr, nullptr);

    // --- row max / inverse softmax sum ---------------------------------------
    rowstat_kernel<<<MROWS, 256>>>(pS, pRmax, pRinv);

    // --- O = softmax(S) @ V; exp on the fly; Vt pre-rounded; O rounded -------
    gemm_mma<true,false><<<dim3(4, 32, Bb), 256, SMEM_SZ>>>(
        pS, pVt, pO, Nn, Cc, Nn, Nn, MROWS,
        (size_t)Nn * Nn, (size_t)Nn, (size_t)Nn * Cc,
        nullptr, pRinv, nullptr, nullptr, 0, 1,
        pRmax, nullptr, nullptr);

    // --- feat_map = gamma * (O @ Wres^T + bres) + x; O pre-rounded -----------
    gemm_mma<false,true><<<dim3(4, 256, 1), 256, SMEM_SZ>>>(
        pO, Wres, featmap, MROWS, Cc, Cc, Cc, Cc, 0, 0, 0,
        bres, nullptr, x, gamma, 0, 0,
        nullptr, nullptr, nullptr);
}